// round 1
// baseline (speedup 1.0000x reference)
#include <cuda_runtime.h>
#include <cuda_bf16.h>
#include <cstdint>

// Problem constants
#define NB    4
#define DIM   32          // output spatial dim (after 2x upsample)
#define SPOS  (DIM*DIM*DIM)     // 32768 positions per sample
#define CIN   256
#define COUT  128
#define TAPS  27
#define TILE_P 64         // spatial positions per block
#define CK    16          // k-chunk (input channels per smem tile)

// Scratch (device globals: allowed, no allocations)
__device__ float g_y1[NB * SPOS * COUT];
__device__ float g_y2[NB * SPOS * COUT];
__device__ float g_part[2][NB * 32 * COUT * 2];
__device__ float g_mean[2][NB * COUT];
__device__ float g_istd[2][NB * COUT];

// ---- packed f32x2 helpers (Blackwell FFMA2) ----
__device__ __forceinline__ unsigned long long fma2(unsigned long long a,
                                                   unsigned long long b,
                                                   unsigned long long c) {
    unsigned long long d;
    asm("fma.rn.f32x2 %0, %1, %2, %3;" : "=l"(d) : "l"(a), "l"(b), "l"(c));
    return d;
}
__device__ __forceinline__ unsigned long long pack2(float x) {
    unsigned long long d;
    asm("mov.b64 %0, {%1, %1};" : "=l"(d) : "f"(x));
    return d;
}

// ---- fused conv kernel ----
// PHASE 1: src = x [4,16,16,16,256] (implicit 2x nearest upsample), dst = g_y1
// PHASE 2: input = concat(relu(instnorm(g_y1)), skip), dst = g_y2
template <int PHASE>
__global__ __launch_bounds__(256) void conv_kernel(
    const float* __restrict__ src,      // PHASE1: x; PHASE2: unused
    const float* __restrict__ skip,     // PHASE2: skip [4,32,32,32,128]
    const float* __restrict__ wgt)      // [4,27,256,128]
{
    __shared__ __align__(16) float As[CK][68];     // padded rows
    __shared__ __align__(16) float Bs[CK][COUT];
    __shared__ float s_mean[COUT];
    __shared__ float s_istd[COUT];

    const int tid = threadIdx.x;
    const int bid = blockIdx.x;
    const int b   = bid >> 9;          // / 512 tiles per sample
    const int p0  = (bid & 511) << 6;  // * TILE_P

    if (PHASE == 2) {
        if (tid < COUT) {
            s_mean[tid] = g_mean[0][b * COUT + tid];
            s_istd[tid] = g_istd[0][b * COUT + tid];
        }
    }

    // A-load mapping: each thread loads 4 channels of one position
    const int lp = tid >> 2;              // 0..63 position in tile
    const int lc = (tid & 3) << 2;        // 0,4,8,12 channel offset in chunk
    const int p  = p0 + lp;
    const int aw = p & 31;
    const int ah = (p >> 5) & 31;
    const int ad = p >> 10;

    // compute mapping: 4 spatial x 8 channels per thread
    const int cg = tid & 15;              // output-channel group (cols cg*8..+7)
    const int sg = tid >> 4;              // spatial group (rows sg*4..+3)

    const float* wb = wgt + b * (TAPS * CIN * COUT);

    unsigned long long acc[4][4];
#pragma unroll
    for (int i = 0; i < 4; i++)
#pragma unroll
        for (int j = 0; j < 4; j++) acc[i][j] = 0ull;

    for (int tap = 0; tap < TAPS; tap++) {
        const int kd = tap / 9;
        const int kh = (tap / 3) % 3;
        const int kw = tap % 3;
        const int id = ad + kd - 1;
        const int ih = ah + kh - 1;
        const int iw = aw + kw - 1;
        const bool valid = ((unsigned)id < 32u) & ((unsigned)ih < 32u) & ((unsigned)iw < 32u);

        int abase;
        if (PHASE == 1) {
            // nearest-upsampled source: floor(coord/2) on the 16^3 grid
            abase = (((b * 16 + (id >> 1)) * 16 + (ih >> 1)) * 16 + (iw >> 1)) * CIN;
        } else {
            abase = ((b * SPOS) + (id * 32 + ih) * 32 + iw) * COUT;  // channel stride 128
        }
        const float* wtap = wb + tap * (CIN * COUT);

        for (int cb = 0; cb < CIN; cb += CK) {
            __syncthreads();
            // ---- load B tile: 16x128 contiguous floats from wtap + cb*128 ----
            {
                const float4* s4 = (const float4*)(wtap + cb * COUT);
                float4 v0 = s4[tid];
                float4 v1 = s4[tid + 256];
                int f0 = tid * 4;
                *(float4*)&Bs[f0 >> 7][f0 & 127] = v0;
                int f1 = f0 + 1024;
                *(float4*)&Bs[f1 >> 7][f1 & 127] = v1;
            }
            // ---- load A tile (fused upsample / norm+relu / concat) ----
            {
                float4 v = make_float4(0.f, 0.f, 0.f, 0.f);
                if (valid) {
                    if (PHASE == 1) {
                        v = *(const float4*)(src + abase + cb + lc);
                    } else {
                        const int c = cb + lc;
                        if (c < COUT) {
                            float4 t = *(const float4*)(g_y1 + abase + c);
                            v.x = fmaxf((t.x - s_mean[c    ]) * s_istd[c    ], 0.f);
                            v.y = fmaxf((t.y - s_mean[c + 1]) * s_istd[c + 1], 0.f);
                            v.z = fmaxf((t.z - s_mean[c + 2]) * s_istd[c + 2], 0.f);
                            v.w = fmaxf((t.w - s_mean[c + 3]) * s_istd[c + 3], 0.f);
                        } else {
                            v = *(const float4*)(skip + abase + (c - COUT));
                        }
                    }
                }
                As[lc + 0][lp] = v.x;
                As[lc + 1][lp] = v.y;
                As[lc + 2][lp] = v.z;
                As[lc + 3][lp] = v.w;
            }
            __syncthreads();
            // ---- compute: 16 k-steps, 4x8 outer product in f32x2 ----
#pragma unroll
            for (int k = 0; k < CK; k++) {
                float4 av = *(const float4*)&As[k][sg << 2];
                unsigned long long a0 = pack2(av.x);
                unsigned long long a1 = pack2(av.y);
                unsigned long long a2 = pack2(av.z);
                unsigned long long a3 = pack2(av.w);
                const ulonglong2* bp = (const ulonglong2*)&Bs[k][cg << 3];
                ulonglong2 bA = bp[0];
                ulonglong2 bB = bp[1];
                acc[0][0] = fma2(a0, bA.x, acc[0][0]);
                acc[0][1] = fma2(a0, bA.y, acc[0][1]);
                acc[0][2] = fma2(a0, bB.x, acc[0][2]);
                acc[0][3] = fma2(a0, bB.y, acc[0][3]);
                acc[1][0] = fma2(a1, bA.x, acc[1][0]);
                acc[1][1] = fma2(a1, bA.y, acc[1][1]);
                acc[1][2] = fma2(a1, bB.x, acc[1][2]);
                acc[1][3] = fma2(a1, bB.y, acc[1][3]);
                acc[2][0] = fma2(a2, bA.x, acc[2][0]);
                acc[2][1] = fma2(a2, bA.y, acc[2][1]);
                acc[2][2] = fma2(a2, bB.x, acc[2][2]);
                acc[2][3] = fma2(a2, bB.y, acc[2][3]);
                acc[3][0] = fma2(a3, bA.x, acc[3][0]);
                acc[3][1] = fma2(a3, bA.y, acc[3][1]);
                acc[3][2] = fma2(a3, bB.x, acc[3][2]);
                acc[3][3] = fma2(a3, bB.y, acc[3][3]);
            }
        }
    }

    // ---- epilogue: raw conv output to scratch ----
    float* dst = (PHASE == 1) ? g_y1 : g_y2;
#pragma unroll
    for (int i = 0; i < 4; i++) {
        int op = ((b * SPOS) + p0 + (sg << 2) + i) * COUT + (cg << 3);
        *(ulonglong2*)(dst + op)     = make_ulonglong2(acc[i][0], acc[i][1]);
        *(ulonglong2*)(dst + op + 4) = make_ulonglong2(acc[i][2], acc[i][3]);
    }
}

// ---- deterministic instance-norm stats: pass 1 (per (b,d) partials) ----
__global__ __launch_bounds__(256) void stats_partial(int phase)
{
    const float* y = phase ? g_y2 : g_y1;
    float* part = g_part[phase];
    const int bd = blockIdx.x;          // 0..127  (b*32 + d)
    const int b = bd >> 5;
    const int d = bd & 31;
    const int c = threadIdx.x & 127;
    const int half = threadIdx.x >> 7;

    const float* base = y + ((b * SPOS) + d * 1024) * COUT;
    float s = 0.f, ss = 0.f;
    const int pstart = half * 512;
#pragma unroll 4
    for (int q = 0; q < 512; q++) {
        float v = base[(pstart + q) * COUT + c];
        s += v;
        ss += v * v;
    }
    __shared__ float sh_s[256];
    __shared__ float sh_q[256];
    sh_s[threadIdx.x] = s;
    sh_q[threadIdx.x] = ss;
    __syncthreads();
    if (half == 0) {
        s  = sh_s[c] + sh_s[c + 128];
        ss = sh_q[c] + sh_q[c + 128];
        part[(bd * COUT + c) * 2 + 0] = s;
        part[(bd * COUT + c) * 2 + 1] = ss;
    }
}

// ---- stats pass 2: fold 32 d-partials, finalize mean / inv-std ----
__global__ void stats_final(int phase)
{
    const int i = threadIdx.x;          // 512 = 4*128
    if (i >= NB * COUT) return;
    const int b = i >> 7;
    const int c = i & 127;
    const float* part = g_part[phase];
    float s = 0.f, ss = 0.f;
    for (int d = 0; d < 32; d++) {
        s  += part[((b * 32 + d) * COUT + c) * 2 + 0];
        ss += part[((b * 32 + d) * COUT + c) * 2 + 1];
    }
    const float inv_n = 1.f / (float)SPOS;
    float m = s * inv_n;
    float var = ss * inv_n - m * m;
    g_mean[phase][i] = m;
    g_istd[phase][i] = rsqrtf(var + 1e-5f);
}

// ---- final elementwise: relu(instnorm(y2)) -> out ----
__global__ __launch_bounds__(256) void finalize_kernel(float* __restrict__ out)
{
    const int i = blockIdx.x * blockDim.x + threadIdx.x;   // float4 index
    const int b = i >> 20;                                 // (SPOS*COUT/4) per sample
    const int c0 = (i * 4) & 127;
    float4 v = ((const float4*)g_y2)[i];
    const float* m = &g_mean[1][b * COUT];
    const float* s = &g_istd[1][b * COUT];
    v.x = fmaxf((v.x - m[c0    ]) * s[c0    ], 0.f);
    v.y = fmaxf((v.y - m[c0 + 1]) * s[c0 + 1], 0.f);
    v.z = fmaxf((v.z - m[c0 + 2]) * s[c0 + 2], 0.f);
    v.w = fmaxf((v.w - m[c0 + 3]) * s[c0 + 3], 0.f);
    ((float4*)out)[i] = v;
}

extern "C" void kernel_launch(void* const* d_in, const int* in_sizes, int n_in,
                              void* d_out, int out_size)
{
    const float* x    = (const float*)d_in[0];
    const float* w1   = (const float*)d_in[1];
    const float* w2   = (const float*)d_in[2];
    const float* skip = (const float*)d_in[3];
    float* out = (float*)d_out;

    const int conv_blocks = NB * (SPOS / TILE_P);   // 2048

    conv_kernel<1><<<conv_blocks, 256>>>(x, nullptr, w1);
    stats_partial<<<NB * 32, 256>>>(0);
    stats_final<<<1, 512>>>(0);
    conv_kernel<2><<<conv_blocks, 256>>>(nullptr, skip, w2);
    stats_partial<<<NB * 32, 256>>>(1);
    stats_final<<<1, 512>>>(1);
    finalize_kernel<<<(NB * SPOS * COUT) / 4 / 256, 256>>>(out);
}

// round 4
// speedup vs baseline: 3.6556x; 3.6556x over previous
#include <cuda_runtime.h>
#include <cuda_bf16.h>
#include <cstdint>

// ---------------- problem constants ----------------
#define NB    4
#define DIM   32
#define SPOS  (DIM*DIM*DIM)      // 32768
#define CIN   256
#define COUT  128
#define TAPS  27
#define NCH   108                // 27 taps * 4 ci-chunks of 64
#define TILE_M 128

#define WT_SZ (NB*TAPS*COUT*CIN)         // 3,538,944
#define AX_SZ (NB*16*16*16*CIN)          // 4,194,304
#define A2_SZ (NB*SPOS*CIN)              // 33,554,432

// smem: A_hi | A_lo | B_hi | B_lo, each 128 rows x 64 bf16 (128B rows, xor-swizzled)
#define SM_A_HI 0
#define SM_A_LO 16384
#define SM_B_HI 32768
#define SM_B_LO 49152
#define SMEM_TOTAL 65536

// ---------------- scratch (device globals: allowed; 16B+ aligned for vector access) ----------------
__device__ __align__(128) float g_y1[NB * SPOS * COUT];
__device__ __align__(128) float g_y2[NB * SPOS * COUT];
__device__ __align__(128) __nv_bfloat16 g_w_hi[2][WT_SZ];
__device__ __align__(128) __nv_bfloat16 g_w_lo[2][WT_SZ];
__device__ __align__(128) __nv_bfloat16 g_ax_hi[AX_SZ];
__device__ __align__(128) __nv_bfloat16 g_ax_lo[AX_SZ];
__device__ __align__(128) __nv_bfloat16 g_a2_hi[A2_SZ];
__device__ __align__(128) __nv_bfloat16 g_a2_lo[A2_SZ];
__device__ __align__(128) float g_part[2][NB * 32 * COUT * 2];
__device__ __align__(128) float g_mean[2][NB * COUT];
__device__ __align__(128) float g_istd[2][NB * COUT];

// ---------------- PTX helpers (sm_80-era only; no tcgen05 — harness targets plain sm_100) ----------------
__device__ __forceinline__ uint32_t smem_to_u32(const void* p) {
    uint32_t a;
    asm("{ .reg .u64 t; cvta.to.shared.u64 t, %1; cvt.u32.u64 %0, t; }" : "=r"(a) : "l"(p));
    return a;
}
#define LDSM4(r, addr) \
    asm volatile("ldmatrix.sync.aligned.m8n8.x4.shared.b16 {%0,%1,%2,%3}, [%4];" \
        : "=r"((r)[0]), "=r"((r)[1]), "=r"((r)[2]), "=r"((r)[3]) : "r"(addr))
#define MMA_BF16(c, a, b0, b1) \
    asm volatile("mma.sync.aligned.m16n8k16.row.col.f32.bf16.bf16.f32 " \
        "{%0,%1,%2,%3}, {%4,%5,%6,%7}, {%8,%9}, {%0,%1,%2,%3};" \
        : "+f"((c)[0]), "+f"((c)[1]), "+f"((c)[2]), "+f"((c)[3]) \
        : "r"((a)[0]), "r"((a)[1]), "r"((a)[2]), "r"((a)[3]), "r"(b0), "r"(b1))

union BF4 { __nv_bfloat16 v[4]; uint2 u; };
__device__ __forceinline__ void split4(const float4& f, uint2& hi, uint2& lo) {
    BF4 h, l;
#pragma unroll
    for (int e = 0; e < 4; e++) {
        float fv = (&f.x)[e];
        __nv_bfloat16 hb = __float2bfloat16(fv);
        h.v[e] = hb;
        l.v[e] = __float2bfloat16(fv - __bfloat162float(hb));
    }
    hi = h.u; lo = l.u;
}

// ---------------- prep: weights fp32 [b,tap,ci,co] -> bf16 hi/lo [b,tap,co,ci] ----------------
__global__ __launch_bounds__(256) void prep_w(const float* __restrict__ w, int which)
{
    int i = blockIdx.x * 256 + threadIdx.x;
    if (i >= WT_SZ) return;
    int co = i & 127;
    int ci = (i >> 7) & 255;
    int bt = i >> 15;
    float v = w[i];
    __nv_bfloat16 h = __float2bfloat16(v);
    __nv_bfloat16 l = __float2bfloat16(v - __bfloat162float(h));
    int o = (bt * COUT + co) * CIN + ci;
    g_w_hi[which][o] = h;
    g_w_lo[which][o] = l;
}

// ---------------- prep: x fp32 -> bf16 hi/lo (16^3 grid) ----------------
__global__ __launch_bounds__(256) void prep_x(const float* __restrict__ x)
{
    int i = blockIdx.x * 256 + threadIdx.x;      // float4 index
    if (i >= AX_SZ / 4) return;
    float4 f = ((const float4*)x)[i];
    uint2 hi, lo;
    split4(f, hi, lo);
    *(uint2*)&g_ax_hi[i * 4] = hi;
    *(uint2*)&g_ax_lo[i * 4] = lo;
}

// ---------------- prep: a2 = concat(relu(instnorm(y1)), skip) -> bf16 hi/lo ----------------
__global__ __launch_bounds__(256) void prep_a2(const float* __restrict__ skip)
{
    int i = blockIdx.x * 256 + threadIdx.x;      // handles 4 elems
    if (i >= A2_SZ / 4) return;
    int i4 = i << 2;
    int b = i4 >> 23;                            // 8.39M elems per sample
    int rem = i4 & ((1 << 23) - 1);
    int pos = rem >> 8;
    int ci = rem & 255;
    float4 f;
    if (ci < COUT) {
        f = *(const float4*)(g_y1 + ((size_t)(b * SPOS + pos)) * COUT + ci);
        const float* m = &g_mean[0][b * COUT + ci];
        const float* s = &g_istd[0][b * COUT + ci];
        f.x = fmaxf((f.x - m[0]) * s[0], 0.f);
        f.y = fmaxf((f.y - m[1]) * s[1], 0.f);
        f.z = fmaxf((f.z - m[2]) * s[2], 0.f);
        f.w = fmaxf((f.w - m[3]) * s[3], 0.f);
    } else {
        f = *(const float4*)(skip + ((size_t)(b * SPOS + pos)) * COUT + (ci - COUT));
    }
    uint2 hi, lo;
    split4(f, hi, lo);
    *(uint2*)&g_a2_hi[i4] = hi;
    *(uint2*)&g_a2_lo[i4] = lo;
}

// ---------------- tensor-core conv via mma.sync (split-bf16) ----------------
// PHASE 1: A = g_ax (16^3 grid, implicit 2x upsample), dst = g_y1
// PHASE 2: A = g_a2 (32^3 grid), dst = g_y2
template <int PHASE>
__global__ void __launch_bounds__(256, 2) conv_mma()
{
    extern __shared__ __align__(1024) char sm[];
    const uint32_t smb = smem_to_u32(sm);
    const int tid  = threadIdx.x;
    const int wid  = tid >> 5;
    const int lane = tid & 31;
    const int b    = blockIdx.x >> 8;
    const int p0   = (blockIdx.x & 255) << 7;

    const __nv_bfloat16* Ah = (PHASE == 1) ? g_ax_hi : g_a2_hi;
    const __nv_bfloat16* Al = (PHASE == 1) ? g_ax_lo : g_a2_lo;
    const __nv_bfloat16* Wh = g_w_hi[PHASE - 1];
    const __nv_bfloat16* Wl = g_w_lo[PHASE - 1];
    float* dst = (PHASE == 1) ? g_y1 : g_y2;

    // loader mapping: row r (0..127), khalf (32 bf16 = 64B)
    const int r = tid >> 1;
    const int khalf = tid & 1;
    const int p = p0 + r;
    const int aw = p & 31, ahy = (p >> 5) & 31, ad = p >> 10;

    // compute mapping: warp tile 32 pos x 64 cout
    const int m0 = (wid >> 1) * 32;
    const int n0 = (wid & 1) * 64;

    float acc[2][8][4];
#pragma unroll
    for (int mt = 0; mt < 2; mt++)
#pragma unroll
        for (int j = 0; j < 8; j++)
#pragma unroll
            for (int e = 0; e < 4; e++) acc[mt][j][e] = 0.f;

    for (int c = 0; c < NCH; c++) {
        const int tap = c >> 2;
        const int ciq = c & 3;
        const int kd = tap / 9, kh = (tap % 9) / 3, kw = tap % 3;
        const int id = ad + kd - 1, ih = ahy + kh - 1, iw = aw + kw - 1;
        const bool valid = ((unsigned)id < 32u) & ((unsigned)ih < 32u) & ((unsigned)iw < 32u);

        size_t abase;
        if (PHASE == 1)
            abase = ((size_t)(((b * 16 + (id >> 1)) * 16 + (ih >> 1)) * 16 + (iw >> 1))) * CIN;
        else
            abase = ((size_t)(b * SPOS + (id * 32 + ih) * 32 + iw)) * CIN;
        abase += ciq * 64 + khalf * 32;
        const size_t wbase = ((size_t)(b * TAPS + tap) * COUT + r) * CIN + ciq * 64 + khalf * 32;

        __syncthreads();
        // ---- fill tiles ----
#pragma unroll
        for (int g = 0; g < 4; g++) {
            const uint32_t cunit = khalf * 4 + g;
            const uint32_t soff = (uint32_t)(r * 128) + ((cunit ^ (r & 7)) << 4);
            uint4 vh = make_uint4(0, 0, 0, 0), vl = make_uint4(0, 0, 0, 0);
            if (valid) {
                vh = *(const uint4*)(Ah + abase + g * 8);
                vl = *(const uint4*)(Al + abase + g * 8);
            }
            *(uint4*)(sm + SM_A_HI + soff) = vh;
            *(uint4*)(sm + SM_A_LO + soff) = vl;
            *(uint4*)(sm + SM_B_HI + soff) = *(const uint4*)(Wh + wbase + g * 8);
            *(uint4*)(sm + SM_B_LO + soff) = *(const uint4*)(Wl + wbase + g * 8);
        }
        __syncthreads();

        // ---- compute: 4 k16 steps ----
#pragma unroll
        for (int kk = 0; kk < 4; kk++) {
            uint32_t ahf[2][4], alf[2][4];
#pragma unroll
            for (int mt = 0; mt < 2; mt++) {
                const uint32_t rowm = (uint32_t)(m0 + mt * 16 + (lane & 15));
                const uint32_t cu = (uint32_t)(kk * 2 + (lane >> 4));
                const uint32_t off = rowm * 128 + ((cu ^ (rowm & 7)) << 4);
                LDSM4(ahf[mt], smb + SM_A_HI + off);
                LDSM4(alf[mt], smb + SM_A_LO + off);
            }
#pragma unroll
            for (int ng = 0; ng < 4; ng++) {
                uint32_t bhf[4], blf[4];
                const uint32_t rown = (uint32_t)(n0 + ng * 16 + (lane & 7) + ((lane >> 4) << 3));
                const uint32_t cu = (uint32_t)(kk * 2 + ((lane >> 3) & 1));
                const uint32_t off = rown * 128 + ((cu ^ (rown & 7)) << 4);
                LDSM4(bhf, smb + SM_B_HI + off);
                LDSM4(blf, smb + SM_B_LO + off);
#pragma unroll
                for (int mt = 0; mt < 2; mt++) {
                    MMA_BF16(acc[mt][ng * 2 + 0], ahf[mt], bhf[0], bhf[1]);
                    MMA_BF16(acc[mt][ng * 2 + 1], ahf[mt], bhf[2], bhf[3]);
                    MMA_BF16(acc[mt][ng * 2 + 0], ahf[mt], blf[0], blf[1]);
                    MMA_BF16(acc[mt][ng * 2 + 1], ahf[mt], blf[2], blf[3]);
                    MMA_BF16(acc[mt][ng * 2 + 0], alf[mt], bhf[0], bhf[1]);
                    MMA_BF16(acc[mt][ng * 2 + 1], alf[mt], bhf[2], bhf[3]);
                }
            }
        }
    }

    // ---- epilogue: write fp32 conv output ----
#pragma unroll
    for (int mt = 0; mt < 2; mt++) {
        const int row = m0 + mt * 16 + (lane >> 2);
        float* d0 = dst + ((size_t)(b * SPOS + p0 + row)) * COUT;
        float* d1 = d0 + 8 * COUT;
#pragma unroll
        for (int j = 0; j < 8; j++) {
            const int col = n0 + j * 8 + (lane & 3) * 2;
            *(float2*)(d0 + col) = make_float2(acc[mt][j][0], acc[mt][j][1]);
            *(float2*)(d1 + col) = make_float2(acc[mt][j][2], acc[mt][j][3]);
        }
    }
}

// ---------------- instance-norm stats (verified in round 1) ----------------
__global__ __launch_bounds__(256) void stats_partial(int phase)
{
    const float* y = phase ? g_y2 : g_y1;
    float* part = g_part[phase];
    const int bd = blockIdx.x;
    const int b = bd >> 5;
    const int d = bd & 31;
    const int c = threadIdx.x & 127;
    const int half = threadIdx.x >> 7;

    const float* base = y + ((size_t)(b * SPOS) + d * 1024) * COUT;
    float s = 0.f, ss = 0.f;
    const int pstart = half * 512;
#pragma unroll 4
    for (int q = 0; q < 512; q++) {
        float v = base[(size_t)(pstart + q) * COUT + c];
        s += v; ss += v * v;
    }
    __shared__ float sh_s[256];
    __shared__ float sh_q[256];
    sh_s[threadIdx.x] = s;
    sh_q[threadIdx.x] = ss;
    __syncthreads();
    if (half == 0) {
        s  = sh_s[c] + sh_s[c + 128];
        ss = sh_q[c] + sh_q[c + 128];
        part[(bd * COUT + c) * 2 + 0] = s;
        part[(bd * COUT + c) * 2 + 1] = ss;
    }
}

__global__ void stats_final(int phase)
{
    const int i = threadIdx.x;
    if (i >= NB * COUT) return;
    const int b = i >> 7;
    const int c = i & 127;
    const float* part = g_part[phase];
    float s = 0.f, ss = 0.f;
    for (int d = 0; d < 32; d++) {
        s  += part[((b * 32 + d) * COUT + c) * 2 + 0];
        ss += part[((b * 32 + d) * COUT + c) * 2 + 1];
    }
    const float inv_n = 1.f / (float)SPOS;
    float m = s * inv_n;
    float var = ss * inv_n - m * m;
    g_mean[phase][i] = m;
    g_istd[phase][i] = rsqrtf(var + 1e-5f);
}

__global__ __launch_bounds__(256) void finalize_kernel(float* __restrict__ out)
{
    const int i = blockIdx.x * blockDim.x + threadIdx.x;
    const int b = i >> 20;
    const int c0 = (i * 4) & 127;
    float4 v = ((const float4*)g_y2)[i];
    const float* m = &g_mean[1][b * COUT];
    const float* s = &g_istd[1][b * COUT];
    v.x = fmaxf((v.x - m[c0    ]) * s[c0    ], 0.f);
    v.y = fmaxf((v.y - m[c0 + 1]) * s[c0 + 1], 0.f);
    v.z = fmaxf((v.z - m[c0 + 2]) * s[c0 + 2], 0.f);
    v.w = fmaxf((v.w - m[c0 + 3]) * s[c0 + 3], 0.f);
    ((float4*)out)[i] = v;
}

// ---------------- host ----------------
extern "C" void kernel_launch(void* const* d_in, const int* in_sizes, int n_in,
                              void* d_out, int out_size)
{
    const float* x    = (const float*)d_in[0];
    const float* w1   = (const float*)d_in[1];
    const float* w2   = (const float*)d_in[2];
    const float* skip = (const float*)d_in[3];
    float* out = (float*)d_out;

    cudaFuncSetAttribute(conv_mma<1>, cudaFuncAttributeMaxDynamicSharedMemorySize, SMEM_TOTAL);
    cudaFuncSetAttribute(conv_mma<2>, cudaFuncAttributeMaxDynamicSharedMemorySize, SMEM_TOTAL);

    prep_w<<<(WT_SZ + 255) / 256, 256>>>(w1, 0);
    prep_w<<<(WT_SZ + 255) / 256, 256>>>(w2, 1);
    prep_x<<<(AX_SZ / 4 + 255) / 256, 256>>>(x);

    conv_mma<1><<<NB * (SPOS / TILE_M), 256, SMEM_TOTAL>>>();
    stats_partial<<<NB * 32, 256>>>(0);
    stats_final<<<1, 512>>>(0);

    prep_a2<<<(A2_SZ / 4 + 255) / 256, 256>>>(skip);
    conv_mma<2><<<NB * (SPOS / TILE_M), 256, SMEM_TOTAL>>>();
    stats_partial<<<NB * 32, 256>>>(1);
    stats_final<<<1, 512>>>(1);
    finalize_kernel<<<(NB * SPOS * COUT) / 4 / 256, 256>>>(out);
}